// round 8
// baseline (speedup 1.0000x reference)
#include <cuda_runtime.h>
#include <math_constants.h>

#define Hdim 768
#define H4   192            // Hdim/4
#define SPL  32             // S splits for stage-1
#define SC   128            // rows per split (S/SPL)
#define WIN  15
#define WLEN 31
#define MAXB 16

// ---------------- scratch (no allocation allowed) ----------------
__device__ float g_pmax[MAXB * SPL * Hdim];   // [b][split][h]
__device__ float g_psum[MAXB * SPL * Hdim];
__device__ float g_pcnt[MAXB * SPL];
__device__ float g_tmax[MAXB * Hdim];         // folded max (clamped >= 0)
__device__ float g_tsum[MAXB * Hdim];         // folded sum

// flag-dispatched integer load (int64 vs int32 storage)
__device__ __forceinline__ long long ld_int(const void* p, long long i, int is64) {
    return is64 ? ((const long long*)p)[i] : (long long)((const int*)p)[i];
}

// Per-warp dtype detection: scan a fixed 256-pair region of word_mask viewed
// as int64. If storage were int32, pair = lo + (hi<<32) with hi random in
// {0,1} -> some value > 1 unless all 256 his are 0 (P = 2^-256). Same region
// for every block -> L2-resident, deterministic.
__device__ __forceinline__ int warp_detect_is64(const void* wm, int lane) {
    const long long* p = (const long long*)wm;
    int bad = 0;
#pragma unroll
    for (int i = 0; i < 8; i++) {
        long long v = p[lane + 32 * i];
        if (v < 0 || v > 1) bad = 1;
    }
    unsigned bm = __ballot_sync(0xffffffffu, bad);
    return bm ? 0 : 1;
}

// block reduce over 192 threads (6 warps) -> result on thread 0
__device__ __forceinline__ float block_reduce_192(float acc, float* sw) {
#pragma unroll
    for (int o = 16; o; o >>= 1) acc += __shfl_xor_sync(0xffffffffu, acc, o);
    const int wid = threadIdx.x >> 5;
    if ((threadIdx.x & 31) == 0) sw[wid] = acc;
    __syncthreads();
    float r = 0.0f;
    if (threadIdx.x == 0) {
#pragma unroll
        for (int i = 0; i < 6; i++) r += sw[i];
    }
    return r;
}

#define ACC1(V, W)                                            \
    do {                                                      \
        float ax = (W) * (V).x, ay = (W) * (V).y,             \
              az = (W) * (V).z, aw = (W) * (V).w;             \
        sm.x += ax; sm.y += ay; sm.z += az; sm.w += aw;       \
        mx.x = fmaxf(mx.x, ax); mx.y = fmaxf(mx.y, ay);       \
        mx.z = fmaxf(mx.z, az); mx.w = fmaxf(mx.w, aw);       \
    } while (0)

// ---------------- main kernel: streaming splits + gap scores --------------
// grid (SPL + G, B), block 192.
//   blockIdx.x <  SPL : mask-compacted streaming max/sum over an S chunk,
//                       8-wide explicit load batches (MLP=8)
//   blockIdx.x >= SPL : one gap score (full-window unconditional loads)
__global__ void __launch_bounds__(H4) main_kernel(
    const float4* __restrict__ seqv, const void* __restrict__ tt,
    const void* __restrict__ wm, const void* __restrict__ gids,
    const float* __restrict__ gW, const float* __restrict__ gb,
    float* __restrict__ out, int S, int G)
{
    const int b   = blockIdx.y;
    const int tid = threadIdx.x;

    if (blockIdx.x < SPL) {
        // ---------------- streaming split ----------------
        const int split = blockIdx.x;
        const int s0    = split * SC;

        __shared__ int   slist[SC + 8];
        __shared__ float swt[SC + 8];
        __shared__ int   s_cnt, s_cnt8;

        if (tid < 32) {
            int is64 = warp_detect_is64(wm, tid);
            int base = 0;
            for (int j = 0; j < SC; j += 32) {
                int row = j + tid;
                long long s = (long long)b * S + s0 + row;
                long long t = ld_int(tt, s, is64);
                long long w = ld_int(wm, s, is64);
                int m = (t == 0 && w != 0);
                unsigned bal = __ballot_sync(0xffffffffu, m);
                if (m) {
                    int pos = base + __popc(bal & ((1u << tid) - 1u));
                    slist[pos] = row;
                    swt[pos]   = 1.0f;
                }
                base += __popc(bal);
            }
            int cnt8 = (base + 7) & ~7;
            // pad entries: alias row 0 of chunk with weight 0 (no contribution)
            for (int e = base + tid; e < cnt8; e += 32) {
                slist[e] = 0;
                swt[e]   = 0.0f;
            }
            if (tid == 0) { s_cnt = base; s_cnt8 = cnt8; }
        }
        __syncthreads();

        const int cnt8 = s_cnt8;
        const float4* base4 = seqv + (long long)(b * S + s0) * H4 + tid;

        float4 mx = make_float4(0.f, 0.f, 0.f, 0.f);
        float4 sm = make_float4(0.f, 0.f, 0.f, 0.f);

#pragma unroll 1
        for (int i = 0; i < cnt8; i += 8) {
            const int r0 = slist[i + 0], r1 = slist[i + 1];
            const int r2 = slist[i + 2], r3 = slist[i + 3];
            const int r4 = slist[i + 4], r5 = slist[i + 5];
            const int r6 = slist[i + 6], r7 = slist[i + 7];
            float4 v0 = base4[(long long)r0 * H4];
            float4 v1 = base4[(long long)r1 * H4];
            float4 v2 = base4[(long long)r2 * H4];
            float4 v3 = base4[(long long)r3 * H4];
            float4 v4 = base4[(long long)r4 * H4];
            float4 v5 = base4[(long long)r5 * H4];
            float4 v6 = base4[(long long)r6 * H4];
            float4 v7 = base4[(long long)r7 * H4];
            const float w0 = swt[i + 0], w1 = swt[i + 1];
            const float w2 = swt[i + 2], w3 = swt[i + 3];
            const float w4 = swt[i + 4], w5 = swt[i + 5];
            const float w6 = swt[i + 6], w7 = swt[i + 7];
            ACC1(v0, w0); ACC1(v1, w1); ACC1(v2, w2); ACC1(v3, w3);
            ACC1(v4, w4); ACC1(v5, w5); ACC1(v6, w6); ACC1(v7, w7);
        }

        const int o = (b * SPL + split) * H4 + tid;     // float4 index
        ((float4*)g_pmax)[o] = mx;
        ((float4*)g_psum)[o] = sm;
        if (tid == 0) g_pcnt[b * SPL + split] = (float)s_cnt;
    } else {
        // ---------------- gap score ----------------
        const int g = blockIdx.x - SPL;
        __shared__ int   sgidx;
        __shared__ float smk[WLEN];     // mask as float
        __shared__ int   srow[WLEN];    // clipped row index
        __shared__ float scnt;
        __shared__ float swred[6];

        if (tid < 32) {
            int is64 = warp_detect_is64(wm, tid);
            int gidx = (int)__shfl_sync(0xffffffffu,
                         (int)ld_int(gids, (long long)b * G + g, is64), 0);
            if (tid == 0) sgidx = gidx;
            float m = 0.0f;
            int s  = gidx - WIN + tid;
            int sc = s < 0 ? 0 : (s >= S ? S - 1 : s);
            if (tid < WLEN) {
                if (s >= 0 && s < S) {
                    long long t = ld_int(tt, (long long)b * S + s, is64);
                    long long w = ld_int(wm, (long long)b * S + s, is64);
                    m = (t == 0 && w != 0) ? 1.0f : 0.0f;
                }
                smk[tid]  = m;
                srow[tid] = sc;
            }
#pragma unroll
            for (int o = 16; o; o >>= 1) m += __shfl_xor_sync(0xffffffffu, m, o);
            if (tid == 0) scnt = m;
        }
        __syncthreads();

        const float invc = 1.0f / scnt;
        const float4* rowb = seqv + (long long)b * S * H4 + tid;
        float4 gv = rowb[(long long)sgidx * H4];

        float4 mx = make_float4(0.f, 0.f, 0.f, 0.f);
        float4 sm = make_float4(0.f, 0.f, 0.f, 0.f);
#pragma unroll
        for (int w2 = 0; w2 < WLEN; w2++) {
            float4 v = rowb[(long long)srow[w2] * H4];
            float  m = smk[w2];
            ACC1(v, m);
        }

        const int h = 4 * tid;
        float acc = gv.x * gW[h]     + gv.y * gW[h + 1]
                  + gv.z * gW[h + 2] + gv.w * gW[h + 3]
                  + mx.x * gW[Hdim + h]     + mx.y * gW[Hdim + h + 1]
                  + mx.z * gW[Hdim + h + 2] + mx.w * gW[Hdim + h + 3]
                  + sm.x * invc * gW[2 * Hdim + h]
                  + sm.y * invc * gW[2 * Hdim + h + 1]
                  + sm.z * invc * gW[2 * Hdim + h + 2]
                  + sm.w * invc * gW[2 * Hdim + h + 3];

        float r = block_reduce_192(acc, swred);
        if (tid == 0) out[b * (G + 1) + 1 + g] = r + gb[0];
    }
}

// ---------------- fold kernel: SPL split partials -> g_tmax / g_tsum ------
// grid (6, B), block 256 = 8 warps; warp w folds splits [w*4, w*4+4) for 32
// contiguous float4 columns; smem tree combines the 8 warps.
__global__ void __launch_bounds__(256) fold_kernel()
{
    const int chunk = blockIdx.x;           // 0..5, 32 float4 cols each
    const int b     = blockIdx.y;
    const int sg    = threadIdx.x >> 5;     // split group 0..7
    const int lane  = threadIdx.x & 31;
    const int col   = chunk * 32 + lane;    // float4 column 0..191

    const float4* pmax4 = (const float4*)g_pmax;
    const float4* psum4 = (const float4*)g_psum;

    float4 mx = make_float4(0.f, 0.f, 0.f, 0.f);
    float4 sm = make_float4(0.f, 0.f, 0.f, 0.f);
#pragma unroll
    for (int j = 0; j < SPL / 8; j++) {
        const int split = sg * (SPL / 8) + j;
        const int o = (b * SPL + split) * H4 + col;
        float4 a = pmax4[o];
        float4 s = psum4[o];
        mx.x = fmaxf(mx.x, a.x); mx.y = fmaxf(mx.y, a.y);
        mx.z = fmaxf(mx.z, a.z); mx.w = fmaxf(mx.w, a.w);
        sm.x += s.x; sm.y += s.y; sm.z += s.z; sm.w += s.w;
    }

    __shared__ float4 smx[8][32];
    __shared__ float4 ssm[8][32];
    smx[sg][lane] = mx;
    ssm[sg][lane] = sm;
    __syncthreads();

    if (sg == 0) {
#pragma unroll
        for (int j = 1; j < 8; j++) {
            float4 a = smx[j][lane];
            float4 s = ssm[j][lane];
            mx.x = fmaxf(mx.x, a.x); mx.y = fmaxf(mx.y, a.y);
            mx.z = fmaxf(mx.z, a.z); mx.w = fmaxf(mx.w, a.w);
            sm.x += s.x; sm.y += s.y; sm.z += s.z; sm.w += s.w;
        }
        ((float4*)g_tmax)[b * H4 + col] = mx;   // mx >= 0 already (init 0)
        ((float4*)g_tsum)[b * H4 + col] = sm;
    }
}

// ---------------- cls kernel: tiny dot over folded vectors ----------------
__global__ void __launch_bounds__(H4) cls_kernel(
    const float* __restrict__ pooled,
    const float* __restrict__ cW, const float* __restrict__ cb,
    float* __restrict__ out, int G)
{
    const int b   = blockIdx.x;
    const int tid = threadIdx.x;
    __shared__ float scnt;
    __shared__ float swred[6];

    if (tid < 32) {
        float c = (tid < SPL) ? g_pcnt[b * SPL + tid] : 0.0f;
#pragma unroll
        for (int o = 16; o; o >>= 1) c += __shfl_xor_sync(0xffffffffu, c, o);
        if (tid == 0) scnt = c;
    }
    __syncthreads();
    const float inv = 1.0f / scnt;

    float4 mx = ((const float4*)g_tmax)[b * H4 + tid];
    float4 sm = ((const float4*)g_tsum)[b * H4 + tid];
    const int h = 4 * tid;
    float acc = pooled[b * Hdim + h]     * cW[h]
              + pooled[b * Hdim + h + 1] * cW[h + 1]
              + pooled[b * Hdim + h + 2] * cW[h + 2]
              + pooled[b * Hdim + h + 3] * cW[h + 3]
              + mx.x * cW[Hdim + h]     + mx.y * cW[Hdim + h + 1]
              + mx.z * cW[Hdim + h + 2] + mx.w * cW[Hdim + h + 3]
              + sm.x * inv * cW[2 * Hdim + h]
              + sm.y * inv * cW[2 * Hdim + h + 1]
              + sm.z * inv * cW[2 * Hdim + h + 2]
              + sm.w * inv * cW[2 * Hdim + h + 3];

    float r = block_reduce_192(acc, swred);
    if (tid == 0) out[b * (G + 1)] = r + cb[0];
}

// ---------------- launch ----------------
extern "C" void kernel_launch(void* const* d_in, const int* in_sizes, int n_in,
                              void* d_out, int out_size)
{
    const float* seq    = (const float*)d_in[0];
    const float* pooled = (const float*)d_in[1];
    const void*  tt     = d_in[2];
    const void*  wm     = d_in[3];
    const void*  gids   = d_in[4];
    const float* gW     = (const float*)d_in[5];
    const float* gb     = (const float*)d_in[6];
    const float* cW     = (const float*)d_in[7];
    const float* cb     = (const float*)d_in[8];
    float* out = (float*)d_out;

    const int B = in_sizes[1] / Hdim;   // 16
    const int S = in_sizes[2] / B;      // 4096
    const int G = in_sizes[4] / B;      // 16

    main_kernel<<<dim3(SPL + G, B), H4>>>((const float4*)seq, tt, wm, gids,
                                          gW, gb, out, S, G);

    fold_kernel<<<dim3(6, B), 256>>>();

    cls_kernel<<<B, H4>>>(pooled, cW, cb, out, G);
}

// round 9
// speedup vs baseline: 1.0010x; 1.0010x over previous
#include <cuda_runtime.h>
#include <math_constants.h>

#define Hdim 768
#define H4   192            // Hdim/4
#define SPL  64             // S splits for stage-1
#define SC   64             // rows per split (S/SPL)
#define WIN  15
#define WLEN 31
#define MAXB 16

// ---------------- scratch (no allocation allowed) ----------------
__device__ float g_pmax[MAXB * SPL * Hdim];   // [b][split][h]
__device__ float g_psum[MAXB * SPL * Hdim];
__device__ float g_pcnt[MAXB * SPL];
__device__ float g_tmax[MAXB * Hdim];         // folded max (clamped >= 0)
__device__ float g_tsum[MAXB * Hdim];         // folded sum

// flag-dispatched integer load (int64 vs int32 storage)
__device__ __forceinline__ long long ld_int(const void* p, long long i, int is64) {
    return is64 ? ((const long long*)p)[i] : (long long)((const int*)p)[i];
}

// Per-warp dtype detection: scan a fixed 256-pair region of word_mask viewed
// as int64. If storage were int32, pair = lo + (hi<<32) with hi random in
// {0,1} -> some value > 1 unless all 256 his are 0 (P = 2^-256). Same region
// for every block -> L2-resident, deterministic.
__device__ __forceinline__ int warp_detect_is64(const void* wm, int lane) {
    const long long* p = (const long long*)wm;
    int bad = 0;
#pragma unroll
    for (int i = 0; i < 8; i++) {
        long long v = p[lane + 32 * i];
        if (v < 0 || v > 1) bad = 1;
    }
    unsigned bm = __ballot_sync(0xffffffffu, bad);
    return bm ? 0 : 1;
}

// block reduce over 192 threads (6 warps) -> result on thread 0
__device__ __forceinline__ float block_reduce_192(float acc, float* sw) {
#pragma unroll
    for (int o = 16; o; o >>= 1) acc += __shfl_xor_sync(0xffffffffu, acc, o);
    const int wid = threadIdx.x >> 5;
    if ((threadIdx.x & 31) == 0) sw[wid] = acc;
    __syncthreads();
    float r = 0.0f;
    if (threadIdx.x == 0) {
#pragma unroll
        for (int i = 0; i < 6; i++) r += sw[i];
    }
    return r;
}

#define ACC1(V, W)                                            \
    do {                                                      \
        float ax = (W) * (V).x, ay = (W) * (V).y,             \
              az = (W) * (V).z, aw = (W) * (V).w;             \
        sm.x += ax; sm.y += ay; sm.z += az; sm.w += aw;       \
        mx.x = fmaxf(mx.x, ax); mx.y = fmaxf(mx.y, ay);       \
        mx.z = fmaxf(mx.z, az); mx.w = fmaxf(mx.w, aw);       \
    } while (0)

// issue 8 independent loads (one batch) into register buffer V
#define LOADB(V, I)                                                     \
    do {                                                                \
        _Pragma("unroll")                                               \
        for (int k = 0; k < 8; k++)                                     \
            V[k] = base4[(long long)slist[(I) + k] * H4];               \
    } while (0)

// accumulate one batch with its weights
#define ACCB(V, I)                                                      \
    do {                                                                \
        _Pragma("unroll")                                               \
        for (int k = 0; k < 8; k++) ACC1(V[k], swt[(I) + k]);           \
    } while (0)

// ---------------- main kernel: gap scores + streaming splits --------------
// grid (G + SPL, B), block 192.
//   blockIdx.x <  G : one gap score (scheduled first -> overlaps the stream)
//   blockIdx.x >= G : mask-compacted streaming max/sum over an S chunk,
//                     software-pipelined 8-wide load batches (continuous MLP)
__global__ void __launch_bounds__(H4) main_kernel(
    const float4* __restrict__ seqv, const void* __restrict__ tt,
    const void* __restrict__ wm, const void* __restrict__ gids,
    const float* __restrict__ gW, const float* __restrict__ gb,
    float* __restrict__ out, int S, int G)
{
    const int b   = blockIdx.y;
    const int tid = threadIdx.x;

    if (blockIdx.x >= G) {
        // ---------------- streaming split ----------------
        const int split = blockIdx.x - G;
        const int s0    = split * SC;

        __shared__ int   slist[SC + 16];
        __shared__ float swt[SC + 16];
        __shared__ int   s_cnt, s_cnt16;

        if (tid < 32) {
            int is64 = warp_detect_is64(wm, tid);
            int base = 0;
            for (int j = 0; j < SC; j += 32) {
                int row = j + tid;
                long long s = (long long)b * S + s0 + row;
                long long t = ld_int(tt, s, is64);
                long long w = ld_int(wm, s, is64);
                int m = (t == 0 && w != 0);
                unsigned bal = __ballot_sync(0xffffffffu, m);
                if (m) {
                    int pos = base + __popc(bal & ((1u << tid) - 1u));
                    slist[pos] = row;
                    swt[pos]   = 1.0f;
                }
                base += __popc(bal);
            }
            int cnt16 = (base + 15) & ~15;
            // pad entries: alias row 0 of chunk with weight 0 (no contribution)
            for (int e = base + tid; e < cnt16; e += 32) {
                slist[e] = 0;
                swt[e]   = 0.0f;
            }
            if (tid == 0) { s_cnt = base; s_cnt16 = cnt16; }
        }
        __syncthreads();

        const int cnt16 = s_cnt16;
        const float4* base4 = seqv + (long long)(b * S + s0) * H4 + tid;

        float4 mx = make_float4(0.f, 0.f, 0.f, 0.f);
        float4 sm = make_float4(0.f, 0.f, 0.f, 0.f);

        if (cnt16 > 0) {
            // software pipeline: while batch A accumulates, batch B is in flight
            float4 vA[8], vB[8];
            LOADB(vA, 0);
            int i = 0;
#pragma unroll 1
            for (; i + 32 <= cnt16; i += 16) {
                LOADB(vB, i + 8);
                ACCB(vA, i);
                LOADB(vA, i + 16);
                ACCB(vB, i + 8);
            }
            // epilogue: 16 rows remain, vA holds rows [i, i+8)
            LOADB(vB, i + 8);
            ACCB(vA, i);
            ACCB(vB, i + 8);
        }

        const int o = (b * SPL + split) * H4 + tid;     // float4 index
        ((float4*)g_pmax)[o] = mx;
        ((float4*)g_psum)[o] = sm;
        if (tid == 0) g_pcnt[b * SPL + split] = (float)s_cnt;
    } else {
        // ---------------- gap score ----------------
        const int g = blockIdx.x;
        __shared__ int   sgidx;
        __shared__ float smk[WLEN];     // mask as float
        __shared__ int   srow[WLEN];    // clipped row index
        __shared__ float scnt;
        __shared__ float swred[6];

        if (tid < 32) {
            int is64 = warp_detect_is64(wm, tid);
            int gidx = (int)__shfl_sync(0xffffffffu,
                         (int)ld_int(gids, (long long)b * G + g, is64), 0);
            if (tid == 0) sgidx = gidx;
            float m = 0.0f;
            int s  = gidx - WIN + tid;
            int sc = s < 0 ? 0 : (s >= S ? S - 1 : s);
            if (tid < WLEN) {
                if (s >= 0 && s < S) {
                    long long t = ld_int(tt, (long long)b * S + s, is64);
                    long long w = ld_int(wm, (long long)b * S + s, is64);
                    m = (t == 0 && w != 0) ? 1.0f : 0.0f;
                }
                smk[tid]  = m;
                srow[tid] = sc;
            }
#pragma unroll
            for (int o = 16; o; o >>= 1) m += __shfl_xor_sync(0xffffffffu, m, o);
            if (tid == 0) scnt = m;
        }
        __syncthreads();

        const float invc = 1.0f / scnt;
        const float4* rowb = seqv + (long long)b * S * H4 + tid;
        float4 gv = rowb[(long long)sgidx * H4];

        float4 mx = make_float4(0.f, 0.f, 0.f, 0.f);
        float4 sm = make_float4(0.f, 0.f, 0.f, 0.f);
#pragma unroll
        for (int w2 = 0; w2 < WLEN; w2++) {
            float4 v = rowb[(long long)srow[w2] * H4];
            float  m = smk[w2];
            ACC1(v, m);
        }

        const int h = 4 * tid;
        float acc = gv.x * gW[h]     + gv.y * gW[h + 1]
                  + gv.z * gW[h + 2] + gv.w * gW[h + 3]
                  + mx.x * gW[Hdim + h]     + mx.y * gW[Hdim + h + 1]
                  + mx.z * gW[Hdim + h + 2] + mx.w * gW[Hdim + h + 3]
                  + sm.x * invc * gW[2 * Hdim + h]
                  + sm.y * invc * gW[2 * Hdim + h + 1]
                  + sm.z * invc * gW[2 * Hdim + h + 2]
                  + sm.w * invc * gW[2 * Hdim + h + 3];

        float r = block_reduce_192(acc, swred);
        if (tid == 0) out[b * (G + 1) + 1 + g] = r + gb[0];
    }
}

// ---------------- fold kernel: SPL split partials -> g_tmax / g_tsum ------
// grid (6, B), block 256 = 8 warps; warp w folds splits [w*8, w*8+8) for 32
// contiguous float4 columns; smem tree combines the 8 warps.
__global__ void __launch_bounds__(256) fold_kernel()
{
    const int chunk = blockIdx.x;           // 0..5, 32 float4 cols each
    const int b     = blockIdx.y;
    const int sg    = threadIdx.x >> 5;     // split group 0..7
    const int lane  = threadIdx.x & 31;
    const int col   = chunk * 32 + lane;    // float4 column 0..191

    const float4* pmax4 = (const float4*)g_pmax;
    const float4* psum4 = (const float4*)g_psum;

    float4 mx = make_float4(0.f, 0.f, 0.f, 0.f);
    float4 sm = make_float4(0.f, 0.f, 0.f, 0.f);
#pragma unroll
    for (int j = 0; j < SPL / 8; j++) {
        const int split = sg * (SPL / 8) + j;
        const int o = (b * SPL + split) * H4 + col;
        float4 a = pmax4[o];
        float4 s = psum4[o];
        mx.x = fmaxf(mx.x, a.x); mx.y = fmaxf(mx.y, a.y);
        mx.z = fmaxf(mx.z, a.z); mx.w = fmaxf(mx.w, a.w);
        sm.x += s.x; sm.y += s.y; sm.z += s.z; sm.w += s.w;
    }

    __shared__ float4 smx[8][32];
    __shared__ float4 ssm[8][32];
    smx[sg][lane] = mx;
    ssm[sg][lane] = sm;
    __syncthreads();

    if (sg == 0) {
#pragma unroll
        for (int j = 1; j < 8; j++) {
            float4 a = smx[j][lane];
            float4 s = ssm[j][lane];
            mx.x = fmaxf(mx.x, a.x); mx.y = fmaxf(mx.y, a.y);
            mx.z = fmaxf(mx.z, a.z); mx.w = fmaxf(mx.w, a.w);
            sm.x += s.x; sm.y += s.y; sm.z += s.z; sm.w += s.w;
        }
        ((float4*)g_tmax)[b * H4 + col] = mx;   // mx >= 0 already (init 0)
        ((float4*)g_tsum)[b * H4 + col] = sm;
    }
}

// ---------------- cls kernel: tiny dot over folded vectors ----------------
__global__ void __launch_bounds__(H4) cls_kernel(
    const float* __restrict__ pooled,
    const float* __restrict__ cW, const float* __restrict__ cb,
    float* __restrict__ out, int G)
{
    const int b   = blockIdx.x;
    const int tid = threadIdx.x;
    __shared__ float scnt;
    __shared__ float swred[6];

    if (tid < 32) {
        float c = 0.0f;
#pragma unroll
        for (int j = tid; j < SPL; j += 32) c += g_pcnt[b * SPL + j];
#pragma unroll
        for (int o = 16; o; o >>= 1) c += __shfl_xor_sync(0xffffffffu, c, o);
        if (tid == 0) scnt = c;
    }
    __syncthreads();
    const float inv = 1.0f / scnt;

    float4 mx = ((const float4*)g_tmax)[b * H4 + tid];
    float4 sm = ((const float4*)g_tsum)[b * H4 + tid];
    const int h = 4 * tid;
    float acc = pooled[b * Hdim + h]     * cW[h]
              + pooled[b * Hdim + h + 1] * cW[h + 1]
              + pooled[b * Hdim + h + 2] * cW[h + 2]
              + pooled[b * Hdim + h + 3] * cW[h + 3]
              + mx.x * cW[Hdim + h]     + mx.y * cW[Hdim + h + 1]
              + mx.z * cW[Hdim + h + 2] + mx.w * cW[Hdim + h + 3]
              + sm.x * inv * cW[2 * Hdim + h]
              + sm.y * inv * cW[2 * Hdim + h + 1]
              + sm.z * inv * cW[2 * Hdim + h + 2]
              + sm.w * inv * cW[2 * Hdim + h + 3];

    float r = block_reduce_192(acc, swred);
    if (tid == 0) out[b * (G + 1)] = r + cb[0];
}

// ---------------- launch ----------------
extern "C" void kernel_launch(void* const* d_in, const int* in_sizes, int n_in,
                              void* d_out, int out_size)
{
    const float* seq    = (const float*)d_in[0];
    const float* pooled = (const float*)d_in[1];
    const void*  tt     = d_in[2];
    const void*  wm     = d_in[3];
    const void*  gids   = d_in[4];
    const float* gW     = (const float*)d_in[5];
    const float* gb     = (const float*)d_in[6];
    const float* cW     = (const float*)d_in[7];
    const float* cb     = (const float*)d_in[8];
    float* out = (float*)d_out;

    const int B = in_sizes[1] / Hdim;   // 16
    const int S = in_sizes[2] / B;      // 4096
    const int G = in_sizes[4] / B;      // 16

    main_kernel<<<dim3(G + SPL, B), H4>>>((const float4*)seq, tt, wm, gids,
                                          gW, gb, out, S, G);

    fold_kernel<<<dim3(6, B), 256>>>();

    cls_kernel<<<B, H4>>>(pooled, cW, cb, out, G);
}

// round 10
// speedup vs baseline: 1.0785x; 1.0774x over previous
#include <cuda_runtime.h>
#include <math_constants.h>

#define Hdim 768
#define H4   192            // Hdim/4
#define SPL  32             // S splits for stage-1
#define SC   128            // rows per split (S/SPL)
#define WIN  15
#define WLEN 31
#define MAXB 16

// ---------------- scratch (no allocation allowed) ----------------
__device__ float g_pmax[MAXB * SPL * Hdim];   // [b][split][h]
__device__ float g_psum[MAXB * SPL * Hdim];
__device__ float g_pcnt[MAXB * SPL];
__device__ float g_tmax[MAXB * Hdim];         // folded max (clamped >= 0)
__device__ float g_tsum[MAXB * Hdim];         // folded sum

// flag-dispatched integer load (int64 vs int32 storage)
__device__ __forceinline__ long long ld_int(const void* p, long long i, int is64) {
    return is64 ? ((const long long*)p)[i] : (long long)((const int*)p)[i];
}

// Per-warp dtype detection: scan a fixed 256-pair region of word_mask viewed
// as int64. If storage were int32, pair = lo + (hi<<32) with hi random in
// {0,1} -> some value > 1 unless all 256 his are 0 (P = 2^-256). Same region
// for every block -> L2-resident, deterministic.
__device__ __forceinline__ int warp_detect_is64(const void* wm, int lane) {
    const long long* p = (const long long*)wm;
    int bad = 0;
#pragma unroll
    for (int i = 0; i < 8; i++) {
        long long v = p[lane + 32 * i];
        if (v < 0 || v > 1) bad = 1;
    }
    unsigned bm = __ballot_sync(0xffffffffu, bad);
    return bm ? 0 : 1;
}

// block reduce over 192 threads (6 warps) -> result on thread 0
__device__ __forceinline__ float block_reduce_192(float acc, float* sw) {
#pragma unroll
    for (int o = 16; o; o >>= 1) acc += __shfl_xor_sync(0xffffffffu, acc, o);
    const int wid = threadIdx.x >> 5;
    if ((threadIdx.x & 31) == 0) sw[wid] = acc;
    __syncthreads();
    float r = 0.0f;
    if (threadIdx.x == 0) {
#pragma unroll
        for (int i = 0; i < 6; i++) r += sw[i];
    }
    return r;
}

#define ACC1(V, W)                                            \
    do {                                                      \
        float ax = (W) * (V).x, ay = (W) * (V).y,             \
              az = (W) * (V).z, aw = (W) * (V).w;             \
        sm.x += ax; sm.y += ay; sm.z += az; sm.w += aw;       \
        mx.x = fmaxf(mx.x, ax); mx.y = fmaxf(mx.y, ay);       \
        mx.z = fmaxf(mx.z, az); mx.w = fmaxf(mx.w, aw);       \
    } while (0)

// issue 8 independent loads (one batch) into register buffer V
#define LOADB(V, I)                                                     \
    do {                                                                \
        _Pragma("unroll")                                               \
        for (int k = 0; k < 8; k++)                                     \
            V[k] = base4[(long long)slist[(I) + k] * H4];               \
    } while (0)

// accumulate one batch with its weights
#define ACCB(V, I)                                                      \
    do {                                                                \
        _Pragma("unroll")                                               \
        for (int k = 0; k < 8; k++) ACC1(V[k], swt[(I) + k]);           \
    } while (0)

// ---------------- main kernel: gap scores + streaming splits --------------
// grid (G + SPL, B), block 192.
//   blockIdx.x <  G : one gap score (scheduled first -> overlaps the stream)
//   blockIdx.x >= G : mask-compacted streaming max/sum over an S chunk,
//                     software-pipelined 8-wide load batches (continuous MLP)
__global__ void __launch_bounds__(H4) main_kernel(
    const float4* __restrict__ seqv, const void* __restrict__ tt,
    const void* __restrict__ wm, const void* __restrict__ gids,
    const float* __restrict__ gW, const float* __restrict__ gb,
    float* __restrict__ out, int S, int G)
{
    const int b   = blockIdx.y;
    const int tid = threadIdx.x;

    if (blockIdx.x >= G) {
        // ---------------- streaming split ----------------
        const int split = blockIdx.x - G;
        const int s0    = split * SC;

        __shared__ int   slist[SC + 16];
        __shared__ float swt[SC + 16];
        __shared__ int   s_cnt, s_cnt16;

        if (tid < 32) {
            int is64 = warp_detect_is64(wm, tid);
            // preload ALL mask values into registers with full MLP,
            // then do register-only ballot compaction (no chained loads)
            long long tv[SC / 32], wv[SC / 32];
#pragma unroll
            for (int j = 0; j < SC / 32; j++) {
                long long s = (long long)b * S + s0 + j * 32 + tid;
                tv[j] = ld_int(tt, s, is64);
                wv[j] = ld_int(wm, s, is64);
            }
            int base = 0;
#pragma unroll
            for (int j = 0; j < SC / 32; j++) {
                int row = j * 32 + tid;
                int m = (tv[j] == 0 && wv[j] != 0);
                unsigned bal = __ballot_sync(0xffffffffu, m);
                if (m) {
                    int pos = base + __popc(bal & ((1u << tid) - 1u));
                    slist[pos] = row;
                    swt[pos]   = 1.0f;
                }
                base += __popc(bal);
            }
            int cnt16 = (base + 15) & ~15;
            // pad entries: alias row 0 of chunk with weight 0 (no contribution)
            for (int e = base + tid; e < cnt16; e += 32) {
                slist[e] = 0;
                swt[e]   = 0.0f;
            }
            if (tid == 0) { s_cnt = base; s_cnt16 = cnt16; }
        }
        __syncthreads();

        const int cnt16 = s_cnt16;
        const float4* base4 = seqv + (long long)(b * S + s0) * H4 + tid;

        float4 mx = make_float4(0.f, 0.f, 0.f, 0.f);
        float4 sm = make_float4(0.f, 0.f, 0.f, 0.f);

        if (cnt16 > 0) {
            // software pipeline: while batch A accumulates, batch B is in flight
            float4 vA[8], vB[8];
            LOADB(vA, 0);
            int i = 0;
#pragma unroll 1
            for (; i + 32 <= cnt16; i += 16) {
                LOADB(vB, i + 8);
                ACCB(vA, i);
                LOADB(vA, i + 16);
                ACCB(vB, i + 8);
            }
            // epilogue: 16 rows remain, vA holds rows [i, i+8)
            LOADB(vB, i + 8);
            ACCB(vA, i);
            ACCB(vB, i + 8);
        }

        const int o = (b * SPL + split) * H4 + tid;     // float4 index
        ((float4*)g_pmax)[o] = mx;
        ((float4*)g_psum)[o] = sm;
        if (tid == 0) g_pcnt[b * SPL + split] = (float)s_cnt;
    } else {
        // ---------------- gap score ----------------
        const int g = blockIdx.x;
        __shared__ int   sgidx;
        __shared__ float smk[WLEN];     // mask as float
        __shared__ int   srow[WLEN];    // clipped row index
        __shared__ float scnt;
        __shared__ float swred[6];

        if (tid < 32) {
            int is64 = warp_detect_is64(wm, tid);
            int gidx = (int)__shfl_sync(0xffffffffu,
                         (int)ld_int(gids, (long long)b * G + g, is64), 0);
            if (tid == 0) sgidx = gidx;
            float m = 0.0f;
            int s  = gidx - WIN + tid;
            int sc = s < 0 ? 0 : (s >= S ? S - 1 : s);
            if (tid < WLEN) {
                if (s >= 0 && s < S) {
                    long long t = ld_int(tt, (long long)b * S + s, is64);
                    long long w = ld_int(wm, (long long)b * S + s, is64);
                    m = (t == 0 && w != 0) ? 1.0f : 0.0f;
                }
                smk[tid]  = m;
                srow[tid] = sc;
            }
#pragma unroll
            for (int o = 16; o; o >>= 1) m += __shfl_xor_sync(0xffffffffu, m, o);
            if (tid == 0) scnt = m;
        }
        __syncthreads();

        const float invc = 1.0f / scnt;
        const float4* rowb = seqv + (long long)b * S * H4 + tid;
        float4 gv = rowb[(long long)sgidx * H4];

        float4 mx = make_float4(0.f, 0.f, 0.f, 0.f);
        float4 sm = make_float4(0.f, 0.f, 0.f, 0.f);
#pragma unroll
        for (int w2 = 0; w2 < WLEN; w2++) {
            float4 v = rowb[(long long)srow[w2] * H4];
            float  m = smk[w2];
            ACC1(v, m);
        }

        const int h = 4 * tid;
        float acc = gv.x * gW[h]     + gv.y * gW[h + 1]
                  + gv.z * gW[h + 2] + gv.w * gW[h + 3]
                  + mx.x * gW[Hdim + h]     + mx.y * gW[Hdim + h + 1]
                  + mx.z * gW[Hdim + h + 2] + mx.w * gW[Hdim + h + 3]
                  + sm.x * invc * gW[2 * Hdim + h]
                  + sm.y * invc * gW[2 * Hdim + h + 1]
                  + sm.z * invc * gW[2 * Hdim + h + 2]
                  + sm.w * invc * gW[2 * Hdim + h + 3];

        float r = block_reduce_192(acc, swred);
        if (tid == 0) out[b * (G + 1) + 1 + g] = r + gb[0];
    }
}

// ---------------- fold kernel: SPL split partials -> g_tmax / g_tsum ------
// grid (6, B), block 256 = 8 warps; warp sg folds SPL/8 splits for 32
// contiguous float4 columns; smem tree combines the 8 warps.
__global__ void __launch_bounds__(256) fold_kernel()
{
    const int chunk = blockIdx.x;           // 0..5, 32 float4 cols each
    const int b     = blockIdx.y;
    const int sg    = threadIdx.x >> 5;     // split group 0..7
    const int lane  = threadIdx.x & 31;
    const int col   = chunk * 32 + lane;    // float4 column 0..191

    const float4* pmax4 = (const float4*)g_pmax;
    const float4* psum4 = (const float4*)g_psum;

    float4 mx = make_float4(0.f, 0.f, 0.f, 0.f);
    float4 sm = make_float4(0.f, 0.f, 0.f, 0.f);
#pragma unroll
    for (int j = 0; j < SPL / 8; j++) {
        const int split = sg * (SPL / 8) + j;
        const int o = (b * SPL + split) * H4 + col;
        float4 a = pmax4[o];
        float4 s = psum4[o];
        mx.x = fmaxf(mx.x, a.x); mx.y = fmaxf(mx.y, a.y);
        mx.z = fmaxf(mx.z, a.z); mx.w = fmaxf(mx.w, a.w);
        sm.x += s.x; sm.y += s.y; sm.z += s.z; sm.w += s.w;
    }

    __shared__ float4 smx[8][32];
    __shared__ float4 ssm[8][32];
    smx[sg][lane] = mx;
    ssm[sg][lane] = sm;
    __syncthreads();

    if (sg == 0) {
#pragma unroll
        for (int j = 1; j < 8; j++) {
            float4 a = smx[j][lane];
            float4 s = ssm[j][lane];
            mx.x = fmaxf(mx.x, a.x); mx.y = fmaxf(mx.y, a.y);
            mx.z = fmaxf(mx.z, a.z); mx.w = fmaxf(mx.w, a.w);
            sm.x += s.x; sm.y += s.y; sm.z += s.z; sm.w += s.w;
        }
        ((float4*)g_tmax)[b * H4 + col] = mx;   // mx >= 0 already (init 0)
        ((float4*)g_tsum)[b * H4 + col] = sm;
    }
}

// ---------------- cls kernel: tiny dot over folded vectors ----------------
__global__ void __launch_bounds__(H4) cls_kernel(
    const float* __restrict__ pooled,
    const float* __restrict__ cW, const float* __restrict__ cb,
    float* __restrict__ out, int G)
{
    const int b   = blockIdx.x;
    const int tid = threadIdx.x;
    __shared__ float scnt;
    __shared__ float swred[6];

    if (tid < 32) {
        float c = 0.0f;
#pragma unroll
        for (int j = tid; j < SPL; j += 32) c += g_pcnt[b * SPL + j];
#pragma unroll
        for (int o = 16; o; o >>= 1) c += __shfl_xor_sync(0xffffffffu, c, o);
        if (tid == 0) scnt = c;
    }
    __syncthreads();
    const float inv = 1.0f / scnt;

    float4 mx = ((const float4*)g_tmax)[b * H4 + tid];
    float4 sm = ((const float4*)g_tsum)[b * H4 + tid];
    const int h = 4 * tid;
    float acc = pooled[b * Hdim + h]     * cW[h]
              + pooled[b * Hdim + h + 1] * cW[h + 1]
              + pooled[b * Hdim + h + 2] * cW[h + 2]
              + pooled[b * Hdim + h + 3] * cW[h + 3]
              + mx.x * cW[Hdim + h]     + mx.y * cW[Hdim + h + 1]
              + mx.z * cW[Hdim + h + 2] + mx.w * cW[Hdim + h + 3]
              + sm.x * inv * cW[2 * Hdim + h]
              + sm.y * inv * cW[2 * Hdim + h + 1]
              + sm.z * inv * cW[2 * Hdim + h + 2]
              + sm.w * inv * cW[2 * Hdim + h + 3];

    float r = block_reduce_192(acc, swred);
    if (tid == 0) out[b * (G + 1)] = r + cb[0];
}

// ---------------- launch ----------------
extern "C" void kernel_launch(void* const* d_in, const int* in_sizes, int n_in,
                              void* d_out, int out_size)
{
    const float* seq    = (const float*)d_in[0];
    const float* pooled = (const float*)d_in[1];
    const void*  tt     = d_in[2];
    const void*  wm     = d_in[3];
    const void*  gids   = d_in[4];
    const float* gW     = (const float*)d_in[5];
    const float* gb     = (const float*)d_in[6];
    const float* cW     = (const float*)d_in[7];
    const float* cb     = (const float*)d_in[8];
    float* out = (float*)d_out;

    const int B = in_sizes[1] / Hdim;   // 16
    const int S = in_sizes[2] / B;      // 4096
    const int G = in_sizes[4] / B;      // 16

    main_kernel<<<dim3(G + SPL, B), H4>>>((const float4*)seq, tt, wm, gids,
                                          gW, gb, out, S, G);

    fold_kernel<<<dim3(6, B), 256>>>();

    cls_kernel<<<B, H4>>>(pooled, cW, cb, out, G);
}